// round 15
// baseline (speedup 1.0000x reference)
#include <cuda_runtime.h>
#include <cuda_fp16.h>
#include <cstdint>

#define FIN 128
#define HID 64
#define NODE_CAP 131072
#define SLOT_CAP 64

// Scratch (allocation-free rule: __device__ globals).
// g_cur is zero at module load; k_agg2 restores the all-zeros invariant each call.
__device__ int                   g_cur[NODE_CAP];
__device__ int                   g_slots[(size_t)NODE_CAP * SLOT_CAP]; // padded CSR: src ids per dst
__device__ __align__(16) __half2 g_hs[(size_t)NODE_CAP * (HID / 2)];  // fp16 (x@W1)[u], UNscaled
__device__ float                 g_zs[NODE_CAP];                      // dinv[u]*z[u]

__device__ __forceinline__ uint32_t packh2(float a, float b) {
    __half2 h = __floats2half2_rn(a, b);
    return *(uint32_t*)&h;
}

// ---------------------------------------------------------------------------
// Edge scatter: FOUR edges per thread, full occupancy (~20 regs).
__global__ void k_scatter(const int* __restrict__ ei, int E, int N) {
    int e0 = blockIdx.x * 1024 + threadIdx.x * 4;
    int s[4], d[4];
    #pragma unroll
    for (int i = 0; i < 4; ++i) {
        int e = e0 + i;
        if (e < E) { s[i] = ei[e]; d[i] = ei[(size_t)E + e]; }
        else       { s[i] = -1;    d[i] = -1; }
    }
    #pragma unroll
    for (int i = 0; i < 4; ++i) {
        if ((unsigned)s[i] < (unsigned)N && (unsigned)d[i] < (unsigned)N) {
            int pos = atomicAdd(&g_cur[d[i]], 1);
            if (pos < SLOT_CAP) g_slots[(size_t)d[i] * SLOT_CAP + pos] = s[i];
        }
    }
}

// ---------------------------------------------------------------------------
// GEMM: g_hs = fp16(x @ W1), fp16 mma m16n8k16. 256 threads (8 warps),
// tile 128 rows x 64 cols. W packed to smem ONCE for all K (single sync);
// A-fragments loaded straight from gmem as float2 k-pairs (no x smem).
__global__ void __launch_bounds__(256) k_gemm(
    const float* __restrict__ x, const float* __restrict__ W1, int N
) {
    __shared__ uint32_t Ws_h[64 * 72];  // [kh 0..63][n 0..63], stride 72 (18KB)
    const int t = threadIdx.x;
    const int w = t >> 5;
    const int lane = t & 31;
    const int gid = lane >> 2;          // group id 0..7
    const int tig = lane & 3;           // thread in group 0..3
    const int rowBase = blockIdx.x * 128;
    const int r0 = w * 16;

    // Pack entire W (128k x 64n) into smem as k-pair half2, stride 72.
    #pragma unroll
    for (int kc = 0; kc < 4; ++kc) {
        int kh = kc * 16 + (t >> 4);    // 0..63
        int n4 = (t & 15) << 2;
        const float4 va = *(const float4*)&W1[(size_t)(2 * kh)     * HID + n4];
        const float4 vb = *(const float4*)&W1[(size_t)(2 * kh + 1) * HID + n4];
        uint4 pk;
        pk.x = packh2(va.x, vb.x);
        pk.y = packh2(va.y, vb.y);
        pk.z = packh2(va.z, vb.z);
        pk.w = packh2(va.w, vb.w);
        *(uint4*)&Ws_h[kh * 72 + n4] = pk;
    }
    __syncthreads();

    float acc[8][4];
    #pragma unroll
    for (int nt = 0; nt < 8; ++nt)
        #pragma unroll
        for (int c = 0; c < 4; ++c) acc[nt][c] = 0.0f;

    const int row0g = rowBase + r0 + gid;
    const int row1g = row0g + 8;
    const bool v0 = row0g < N;
    const bool v1 = row1g < N;
    const float* xr0 = x + (size_t)row0g * FIN;
    const float* xr1 = x + (size_t)row1g * FIN;

    #pragma unroll
    for (int kc = 0; kc < 4; ++kc) {
        #pragma unroll
        for (int ks = 0; ks < 2; ++ks) {
            const int kh0 = kc * 16 + ks * 8;
            const int k0 = 2 * (kh0 + tig);   // fragment k-pair base
            float2 z2 = make_float2(0.f, 0.f);
            float2 f0 = v0 ? *(const float2*)&xr0[k0]     : z2;
            float2 f1 = v1 ? *(const float2*)&xr1[k0]     : z2;
            float2 f2 = v0 ? *(const float2*)&xr0[k0 + 8] : z2;
            float2 f3 = v1 ? *(const float2*)&xr1[k0 + 8] : z2;
            uint32_t a0 = packh2(f0.x, f0.y);
            uint32_t a1 = packh2(f1.x, f1.y);
            uint32_t a2 = packh2(f2.x, f2.y);
            uint32_t a3 = packh2(f3.x, f3.y);
            #pragma unroll
            for (int nt = 0; nt < 8; ++nt) {
                uint32_t b0 = Ws_h[(kh0 + tig)     * 72 + nt * 8 + gid];
                uint32_t b1 = Ws_h[(kh0 + 4 + tig) * 72 + nt * 8 + gid];
                asm("mma.sync.aligned.m16n8k16.row.col.f32.f16.f16.f32 "
                    "{%0,%1,%2,%3}, {%4,%5,%6,%7}, {%8,%9}, {%0,%1,%2,%3};"
                    : "+f"(acc[nt][0]), "+f"(acc[nt][1]),
                      "+f"(acc[nt][2]), "+f"(acc[nt][3])
                    : "r"(a0), "r"(a1), "r"(a2), "r"(a3), "r"(b0), "r"(b1));
            }
        }
    }
    #pragma unroll
    for (int nt = 0; nt < 8; ++nt) {
        int c = nt * 4 + tig;   // half2 column index (HID/2 = 32 per row)
        if (v0) g_hs[(size_t)row0g * 32 + c] = __floats2half2_rn(acc[nt][0], acc[nt][1]);
        if (v1) g_hs[(size_t)row1g * 32 + c] = __floats2half2_rn(acc[nt][2], acc[nt][3]);
    }
}

// ---------------------------------------------------------------------------
// Layer-1 aggregation + epilogue + layer-2 GEMV, fused. One warp per node.
// dinv computed inline from g_cur (degree). Lane covers features (2l, 2l+1).
__global__ void k_agg1(const float* __restrict__ b1,
                       const float* __restrict__ W2, int N) {
    int w = (blockIdx.x * blockDim.x + threadIdx.x) >> 5;
    int lane = threadIdx.x & 31;
    if (w >= N) return;
    int deg = g_cur[w];
    float dv = rsqrtf((float)deg + 1.0f);
    float2 hv = __half22float2(g_hs[(size_t)w * 32 + lane]);
    float2 a = make_float2(hv.x * dv, hv.y * dv);             // self-loop seed
    const int* slots = &g_slots[(size_t)w * SLOT_CAP];
    const int cnt = min(deg, SLOT_CAP);
    for (int j0 = 0; j0 < cnt; j0 += 32) {
        int m = min(32, cnt - j0);
        int s = 0; float dvs = 0.f;
        if (j0 + lane < cnt) {
            s = slots[j0 + lane];
            dvs = rsqrtf((float)g_cur[s] + 1.0f);
        }
        #pragma unroll 16
        for (int i = 0; i < m; ++i) {
            int   si  = __shfl_sync(0xffffffffu, s, i);
            float dvi = __shfl_sync(0xffffffffu, dvs, i);
            float2 v = __half22float2(g_hs[(size_t)si * 32 + lane]);
            a.x = fmaf(v.x, dvi, a.x);
            a.y = fmaf(v.y, dvi, a.y);
        }
    }
    float h0 = fmaxf(fmaf(dv, a.x, __ldg(&b1[2 * lane])),     0.0f);
    float h1 = fmaxf(fmaf(dv, a.y, __ldg(&b1[2 * lane + 1])), 0.0f);
    float z = h0 * __ldg(&W2[2 * lane]) + h1 * __ldg(&W2[2 * lane + 1]);
    #pragma unroll
    for (int o = 16; o > 0; o >>= 1) z += __shfl_xor_sync(0xffffffffu, z, o);
    if (lane == 0) g_zs[w] = dv * z;
}

// ---------------------------------------------------------------------------
// Layer-2 scalar aggregation + finalize. EIGHT lanes per node (best measured).
// Lane 0 restores g_cur[v] = 0 for the next graph replay.
__global__ void k_agg2(float* __restrict__ out, const float* __restrict__ b2, int N) {
    int idx = blockIdx.x * blockDim.x + threadIdx.x;
    int v = idx >> 3;
    int l = idx & 7;
    if (v >= N) return;
    int deg = g_cur[v];
    int cnt = min(deg, SLOT_CAP);
    const int* slots = &g_slots[(size_t)v * SLOT_CAP];
    float sum = 0.0f;
    for (int j = l; j < cnt; j += 8) sum += g_zs[slots[j]];
    #pragma unroll
    for (int o = 4; o > 0; o >>= 1) sum += __shfl_down_sync(0xffffffffu, sum, o, 8);
    if (l == 0) {
        sum += g_zs[v];    // self loop
        out[v] = fmaf(rsqrtf((float)deg + 1.0f), sum, __ldg(b2));
        g_cur[v] = 0;      // maintain all-zeros invariant for next call
    }
}

// ---------------------------------------------------------------------------
extern "C" void kernel_launch(void* const* d_in, const int* in_sizes, int n_in,
                              void* d_out, int out_size) {
    const float* x  = (const float*)d_in[0];
    const int*   ei = (const int*)d_in[1];      // edge_index int32
    const float* W1 = (const float*)d_in[2];
    const float* b1 = (const float*)d_in[3];
    const float* W2 = (const float*)d_in[4];
    const float* b2 = (const float*)d_in[5];
    float*       out = (float*)d_out;

    const int N = in_sizes[0] / FIN;
    const int E = in_sizes[1] / 2;

    // Fork a side stream: GEMM (DRAM-bound) runs concurrently with the
    // full-occupancy scatter. Each kernel gets its own register budget.
    cudaStream_t s2;
    cudaStreamCreateWithFlags(&s2, cudaStreamNonBlocking);
    cudaEvent_t eFork, eJoin;
    cudaEventCreateWithFlags(&eFork, cudaEventDisableTiming);
    cudaEventCreateWithFlags(&eJoin, cudaEventDisableTiming);

    cudaEventRecord(eFork, 0);
    cudaStreamWaitEvent(s2, eFork, 0);
    k_gemm<<<(N + 127) / 128, 256, 0, s2>>>(x, W1, N);
    cudaEventRecord(eJoin, s2);

    k_scatter<<<(E + 1023) / 1024, 256>>>(ei, E, N);

    cudaStreamWaitEvent(0, eJoin, 0);
    k_agg1   <<<(N * 32 + 255) / 256, 256>>>(b1, W2, N);
    k_agg2   <<<(N * 8 + 255) / 256, 256>>>(out, b2, N);
}

// round 16
// speedup vs baseline: 1.0352x; 1.0352x over previous
#include <cuda_runtime.h>
#include <cuda_fp16.h>
#include <cstdint>

#define FIN 128
#define HID 64
#define NODE_CAP 131072
#define SLOT_CAP 64

// Scratch (allocation-free rule: __device__ globals).
// g_cur is zero at module load; k_agg2 restores the all-zeros invariant each call.
__device__ int                   g_cur[NODE_CAP];
__device__ int                   g_slots[(size_t)NODE_CAP * SLOT_CAP]; // padded CSR: src ids per dst
__device__ __align__(16) __half2 g_hs[(size_t)NODE_CAP * (HID / 2)];  // fp16 (x@W1)[u], UNscaled
__device__ float                 g_zs[NODE_CAP];                      // dinv[u]*z[u]

__device__ __forceinline__ uint32_t packh2(float a, float b) {
    __half2 h = __floats2half2_rn(a, b);
    return *(uint32_t*)&h;
}
__device__ __forceinline__ uint32_t packh2f2(float2 v) { return packh2(v.x, v.y); }

__device__ __forceinline__ uint32_t su32(const void* p) {
    uint32_t a;
    asm("{ .reg .u64 t; cvta.to.shared.u64 t, %1; cvt.u32.u64 %0, t; }"
        : "=r"(a) : "l"(p));
    return a;
}

// ---------------------------------------------------------------------------
// Edge scatter: FOUR edges per thread, full occupancy (~20 regs).
__global__ void k_scatter(const int* __restrict__ ei, int E, int N) {
    int e0 = blockIdx.x * 1024 + threadIdx.x * 4;
    int s[4], d[4];
    #pragma unroll
    for (int i = 0; i < 4; ++i) {
        int e = e0 + i;
        if (e < E) { s[i] = ei[e]; d[i] = ei[(size_t)E + e]; }
        else       { s[i] = -1;    d[i] = -1; }
    }
    #pragma unroll
    for (int i = 0; i < 4; ++i) {
        if ((unsigned)s[i] < (unsigned)N && (unsigned)d[i] < (unsigned)N) {
            int pos = atomicAdd(&g_cur[d[i]], 1);
            if (pos < SLOT_CAP) g_slots[(size_t)d[i] * SLOT_CAP + pos] = s[i];
        }
    }
}

// ---------------------------------------------------------------------------
// GEMM: g_hs = fp16(x @ W1), fp16 mma m16n8k16, cp.async double-buffered.
// 256 threads (8 warps), tile 128 rows x 64 cols. W packed to smem once
// (18KB); x streamed in 8 chunks of k=16 into 2 x 12KB fp32 buffers
// (row stride 24 floats -> conflict-free float2 fragment loads).
__global__ void __launch_bounds__(256) k_gemm(
    const float* __restrict__ x, const float* __restrict__ W1, int N
) {
    __shared__ uint32_t Ws_h[64 * 72];      // packed half2 W, stride 72
    __shared__ float    xs[2][128 * 24];    // fp32 x chunks, stride 24
    const int t = threadIdx.x;
    const int w = t >> 5;
    const int lane = t & 31;
    const int gid = lane >> 2;          // group id 0..7
    const int tig = lane & 3;           // thread in group 0..3
    const int rowBase = blockIdx.x * 128;
    const int r0 = w * 16;

    // Per-thread cp.async job: 2 float4 per chunk (512 per chunk).
    const int crow = t >> 2;            // rows t/4 and t/4+64
    const int cq   = (t & 3) << 2;      // float offset 0/4/8/12 within chunk
    const int grow0 = rowBase + crow;
    const int grow1 = rowBase + crow + 64;
    const int sz0 = (grow0 < N) ? 16 : 0;
    const int sz1 = (grow1 < N) ? 16 : 0;
    const uint32_t dst0 = su32(&xs[0][crow * 24 + cq]);
    const uint32_t dst1 = su32(&xs[0][(crow + 64) * 24 + cq]);
    const uint32_t bufStride = (uint32_t)(128 * 24 * sizeof(float));

    // Issue chunk 0.
    {
        const float* s0 = x + (size_t)grow0 * FIN + cq;
        const float* s1 = x + (size_t)grow1 * FIN + cq;
        asm volatile("cp.async.cg.shared.global [%0], [%1], 16, %2;" :: "r"(dst0), "l"(s0), "r"(sz0) : "memory");
        asm volatile("cp.async.cg.shared.global [%0], [%1], 16, %2;" :: "r"(dst1), "l"(s1), "r"(sz1) : "memory");
        asm volatile("cp.async.commit_group;" ::: "memory");
    }

    // Pack W (128k x 64n) as k-pair half2 while chunk 0 is in flight.
    #pragma unroll
    for (int kc = 0; kc < 4; ++kc) {
        int kh = kc * 16 + (t >> 4);    // 0..63
        int n4 = (t & 15) << 2;
        const float4 va = *(const float4*)&W1[(size_t)(2 * kh)     * HID + n4];
        const float4 vb = *(const float4*)&W1[(size_t)(2 * kh + 1) * HID + n4];
        uint4 pk;
        pk.x = packh2(va.x, vb.x);
        pk.y = packh2(va.y, vb.y);
        pk.z = packh2(va.z, vb.z);
        pk.w = packh2(va.w, vb.w);
        *(uint4*)&Ws_h[kh * 72 + n4] = pk;
    }

    float acc[8][4];
    #pragma unroll
    for (int nt = 0; nt < 8; ++nt)
        #pragma unroll
        for (int c = 0; c < 4; ++c) acc[nt][c] = 0.0f;

    #pragma unroll
    for (int kc = 0; kc < 8; ++kc) {
        if (kc < 7) {   // issue chunk kc+1 into buffer (kc+1)&1
            int b = (kc + 1) & 1;
            const float* s0 = x + (size_t)grow0 * FIN + (kc + 1) * 16 + cq;
            const float* s1 = x + (size_t)grow1 * FIN + (kc + 1) * 16 + cq;
            asm volatile("cp.async.cg.shared.global [%0], [%1], 16, %2;" :: "r"(dst0 + b * bufStride), "l"(s0), "r"(sz0) : "memory");
            asm volatile("cp.async.cg.shared.global [%0], [%1], 16, %2;" :: "r"(dst1 + b * bufStride), "l"(s1), "r"(sz1) : "memory");
            asm volatile("cp.async.commit_group;" ::: "memory");
            asm volatile("cp.async.wait_group 1;" ::: "memory");
        } else {
            asm volatile("cp.async.wait_group 0;" ::: "memory");
        }
        __syncthreads();
        const float* xb = xs[kc & 1];
        // A fragments for this k=16 chunk (fp32 -> half2 pack in regs).
        float2 lo0 = *(const float2*)&xb[(r0 + gid)     * 24 + 2 * tig];
        float2 lo1 = *(const float2*)&xb[(r0 + 8 + gid) * 24 + 2 * tig];
        float2 hi0 = *(const float2*)&xb[(r0 + gid)     * 24 + 2 * tig + 8];
        float2 hi1 = *(const float2*)&xb[(r0 + 8 + gid) * 24 + 2 * tig + 8];
        uint32_t a0 = packh2f2(lo0);
        uint32_t a1 = packh2f2(lo1);
        uint32_t a2 = packh2f2(hi0);
        uint32_t a3 = packh2f2(hi1);
        const int kh0 = kc * 8;
        #pragma unroll
        for (int nt = 0; nt < 8; ++nt) {
            uint32_t b0 = Ws_h[(kh0 + tig)     * 72 + nt * 8 + gid];
            uint32_t b1 = Ws_h[(kh0 + 4 + tig) * 72 + nt * 8 + gid];
            asm("mma.sync.aligned.m16n8k16.row.col.f32.f16.f16.f32 "
                "{%0,%1,%2,%3}, {%4,%5,%6,%7}, {%8,%9}, {%0,%1,%2,%3};"
                : "+f"(acc[nt][0]), "+f"(acc[nt][1]),
                  "+f"(acc[nt][2]), "+f"(acc[nt][3])
                : "r"(a0), "r"(a1), "r"(a2), "r"(a3), "r"(b0), "r"(b1));
        }
        __syncthreads();
    }

    int row0 = rowBase + r0 + gid;
    int row1 = row0 + 8;
    #pragma unroll
    for (int nt = 0; nt < 8; ++nt) {
        int c = nt * 4 + tig;   // half2 column index (HID/2 = 32 per row)
        if (row0 < N) g_hs[(size_t)row0 * 32 + c] = __floats2half2_rn(acc[nt][0], acc[nt][1]);
        if (row1 < N) g_hs[(size_t)row1 * 32 + c] = __floats2half2_rn(acc[nt][2], acc[nt][3]);
    }
}

// ---------------------------------------------------------------------------
// Layer-1 aggregation + epilogue + layer-2 GEMV, fused. One warp per node.
// dinv computed inline from g_cur (degree). Lane covers features (2l, 2l+1).
__global__ void k_agg1(const float* __restrict__ b1,
                       const float* __restrict__ W2, int N) {
    int w = (blockIdx.x * blockDim.x + threadIdx.x) >> 5;
    int lane = threadIdx.x & 31;
    if (w >= N) return;
    int deg = g_cur[w];
    float dv = rsqrtf((float)deg + 1.0f);
    float2 hv = __half22float2(g_hs[(size_t)w * 32 + lane]);
    float2 a = make_float2(hv.x * dv, hv.y * dv);             // self-loop seed
    const int* slots = &g_slots[(size_t)w * SLOT_CAP];
    const int cnt = min(deg, SLOT_CAP);
    for (int j0 = 0; j0 < cnt; j0 += 32) {
        int m = min(32, cnt - j0);
        int s = 0; float dvs = 0.f;
        if (j0 + lane < cnt) {
            s = slots[j0 + lane];
            dvs = rsqrtf((float)g_cur[s] + 1.0f);
        }
        #pragma unroll 16
        for (int i = 0; i < m; ++i) {
            int   si  = __shfl_sync(0xffffffffu, s, i);
            float dvi = __shfl_sync(0xffffffffu, dvs, i);
            float2 v = __half22float2(g_hs[(size_t)si * 32 + lane]);
            a.x = fmaf(v.x, dvi, a.x);
            a.y = fmaf(v.y, dvi, a.y);
        }
    }
    float h0 = fmaxf(fmaf(dv, a.x, __ldg(&b1[2 * lane])),     0.0f);
    float h1 = fmaxf(fmaf(dv, a.y, __ldg(&b1[2 * lane + 1])), 0.0f);
    float z = h0 * __ldg(&W2[2 * lane]) + h1 * __ldg(&W2[2 * lane + 1]);
    #pragma unroll
    for (int o = 16; o > 0; o >>= 1) z += __shfl_xor_sync(0xffffffffu, z, o);
    if (lane == 0) g_zs[w] = dv * z;
}

// ---------------------------------------------------------------------------
// Layer-2 scalar aggregation + finalize. EIGHT lanes per node (best measured).
// Lane 0 restores g_cur[v] = 0 for the next graph replay.
__global__ void k_agg2(float* __restrict__ out, const float* __restrict__ b2, int N) {
    int idx = blockIdx.x * blockDim.x + threadIdx.x;
    int v = idx >> 3;
    int l = idx & 7;
    if (v >= N) return;
    int deg = g_cur[v];
    int cnt = min(deg, SLOT_CAP);
    const int* slots = &g_slots[(size_t)v * SLOT_CAP];
    float sum = 0.0f;
    for (int j = l; j < cnt; j += 8) sum += g_zs[slots[j]];
    #pragma unroll
    for (int o = 4; o > 0; o >>= 1) sum += __shfl_down_sync(0xffffffffu, sum, o, 8);
    if (l == 0) {
        sum += g_zs[v];    // self loop
        out[v] = fmaf(rsqrtf((float)deg + 1.0f), sum, __ldg(b2));
        g_cur[v] = 0;      // maintain all-zeros invariant for next call
    }
}

// ---------------------------------------------------------------------------
extern "C" void kernel_launch(void* const* d_in, const int* in_sizes, int n_in,
                              void* d_out, int out_size) {
    const float* x  = (const float*)d_in[0];
    const int*   ei = (const int*)d_in[1];      // edge_index int32
    const float* W1 = (const float*)d_in[2];
    const float* b1 = (const float*)d_in[3];
    const float* W2 = (const float*)d_in[4];
    const float* b2 = (const float*)d_in[5];
    float*       out = (float*)d_out;

    const int N = in_sizes[0] / FIN;
    const int E = in_sizes[1] / 2;

    // Fork a side stream: GEMM (DRAM-bound) runs concurrently with the
    // full-occupancy scatter. Each kernel gets its own register budget.
    cudaStream_t s2;
    cudaStreamCreateWithFlags(&s2, cudaStreamNonBlocking);
    cudaEvent_t eFork, eJoin;
    cudaEventCreateWithFlags(&eFork, cudaEventDisableTiming);
    cudaEventCreateWithFlags(&eJoin, cudaEventDisableTiming);

    cudaEventRecord(eFork, 0);
    cudaStreamWaitEvent(s2, eFork, 0);
    k_gemm<<<(N + 127) / 128, 256, 0, s2>>>(x, W1, N);
    cudaEventRecord(eJoin, s2);

    k_scatter<<<(E + 1023) / 1024, 256>>>(ei, E, N);

    cudaStreamWaitEvent(0, eJoin, 0);
    k_agg1   <<<(N * 32 + 255) / 256, 256>>>(b1, W2, N);
    k_agg2   <<<(N * 8 + 255) / 256, 256>>>(out, b2, N);
}

// round 17
// speedup vs baseline: 1.1316x; 1.0931x over previous
#include <cuda_runtime.h>
#include <cuda_fp16.h>
#include <cstdint>

#define FIN 128
#define HID 64
#define NODE_CAP 131072
#define SLOT_CAP 64

// Scratch (allocation-free rule: __device__ globals).
// g_cur is zero at module load; k_agg2 restores the all-zeros invariant each call.
__device__ int                   g_cur[NODE_CAP];
__device__ int                   g_slots[(size_t)NODE_CAP * SLOT_CAP]; // padded CSR: src ids per dst
__device__ __align__(16) __half2 g_hs[(size_t)NODE_CAP * (HID / 2)];  // fp16 (x@W1)[u], UNscaled
__device__ float                 g_zs[NODE_CAP];                      // dinv[u]*z[u]

__device__ __forceinline__ uint32_t packh2(float a, float b) {
    __half2 h = __floats2half2_rn(a, b);
    return *(uint32_t*)&h;
}
__device__ __forceinline__ uint32_t packh2f2(float2 v) { return packh2(v.x, v.y); }

__device__ __forceinline__ uint32_t su32(const void* p) {
    uint32_t a;
    asm("{ .reg .u64 t; cvta.to.shared.u64 t, %1; cvt.u32.u64 %0, t; }"
        : "=r"(a) : "l"(p));
    return a;
}

// ---------------------------------------------------------------------------
// Edge scatter: FOUR edges per thread, full occupancy (~20 regs).
__global__ void k_scatter(const int* __restrict__ ei, int E, int N) {
    int e0 = blockIdx.x * 1024 + threadIdx.x * 4;
    int s[4], d[4];
    #pragma unroll
    for (int i = 0; i < 4; ++i) {
        int e = e0 + i;
        if (e < E) { s[i] = ei[e]; d[i] = ei[(size_t)E + e]; }
        else       { s[i] = -1;    d[i] = -1; }
    }
    #pragma unroll
    for (int i = 0; i < 4; ++i) {
        if ((unsigned)s[i] < (unsigned)N && (unsigned)d[i] < (unsigned)N) {
            int pos = atomicAdd(&g_cur[d[i]], 1);
            if (pos < SLOT_CAP) g_slots[(size_t)d[i] * SLOT_CAP + pos] = s[i];
        }
    }
}

// ---------------------------------------------------------------------------
// GEMM: g_hs = fp16(x @ W1), fp16 mma m16n8k16, cp.async double-buffered.
__global__ void __launch_bounds__(256) k_gemm(
    const float* __restrict__ x, const float* __restrict__ W1, int N
) {
    __shared__ uint32_t Ws_h[64 * 72];      // packed half2 W, stride 72
    __shared__ float    xs[2][128 * 24];    // fp32 x chunks, stride 24
    const int t = threadIdx.x;
    const int w = t >> 5;
    const int lane = t & 31;
    const int gid = lane >> 2;
    const int tig = lane & 3;
    const int rowBase = blockIdx.x * 128;
    const int r0 = w * 16;

    const int crow = t >> 2;
    const int cq   = (t & 3) << 2;
    const int grow0 = rowBase + crow;
    const int grow1 = rowBase + crow + 64;
    const int sz0 = (grow0 < N) ? 16 : 0;
    const int sz1 = (grow1 < N) ? 16 : 0;
    const uint32_t dst0 = su32(&xs[0][crow * 24 + cq]);
    const uint32_t dst1 = su32(&xs[0][(crow + 64) * 24 + cq]);
    const uint32_t bufStride = (uint32_t)(128 * 24 * sizeof(float));

    {
        const float* s0 = x + (size_t)grow0 * FIN + cq;
        const float* s1 = x + (size_t)grow1 * FIN + cq;
        asm volatile("cp.async.cg.shared.global [%0], [%1], 16, %2;" :: "r"(dst0), "l"(s0), "r"(sz0) : "memory");
        asm volatile("cp.async.cg.shared.global [%0], [%1], 16, %2;" :: "r"(dst1), "l"(s1), "r"(sz1) : "memory");
        asm volatile("cp.async.commit_group;" ::: "memory");
    }

    #pragma unroll
    for (int kc = 0; kc < 4; ++kc) {
        int kh = kc * 16 + (t >> 4);
        int n4 = (t & 15) << 2;
        const float4 va = *(const float4*)&W1[(size_t)(2 * kh)     * HID + n4];
        const float4 vb = *(const float4*)&W1[(size_t)(2 * kh + 1) * HID + n4];
        uint4 pk;
        pk.x = packh2(va.x, vb.x);
        pk.y = packh2(va.y, vb.y);
        pk.z = packh2(va.z, vb.z);
        pk.w = packh2(va.w, vb.w);
        *(uint4*)&Ws_h[kh * 72 + n4] = pk;
    }

    float acc[8][4];
    #pragma unroll
    for (int nt = 0; nt < 8; ++nt)
        #pragma unroll
        for (int c = 0; c < 4; ++c) acc[nt][c] = 0.0f;

    #pragma unroll
    for (int kc = 0; kc < 8; ++kc) {
        if (kc < 7) {
            int b = (kc + 1) & 1;
            const float* s0 = x + (size_t)grow0 * FIN + (kc + 1) * 16 + cq;
            const float* s1 = x + (size_t)grow1 * FIN + (kc + 1) * 16 + cq;
            asm volatile("cp.async.cg.shared.global [%0], [%1], 16, %2;" :: "r"(dst0 + b * bufStride), "l"(s0), "r"(sz0) : "memory");
            asm volatile("cp.async.cg.shared.global [%0], [%1], 16, %2;" :: "r"(dst1 + b * bufStride), "l"(s1), "r"(sz1) : "memory");
            asm volatile("cp.async.commit_group;" ::: "memory");
            asm volatile("cp.async.wait_group 1;" ::: "memory");
        } else {
            asm volatile("cp.async.wait_group 0;" ::: "memory");
        }
        __syncthreads();
        const float* xb = xs[kc & 1];
        float2 lo0 = *(const float2*)&xb[(r0 + gid)     * 24 + 2 * tig];
        float2 lo1 = *(const float2*)&xb[(r0 + 8 + gid) * 24 + 2 * tig];
        float2 hi0 = *(const float2*)&xb[(r0 + gid)     * 24 + 2 * tig + 8];
        float2 hi1 = *(const float2*)&xb[(r0 + 8 + gid) * 24 + 2 * tig + 8];
        uint32_t a0 = packh2f2(lo0);
        uint32_t a1 = packh2f2(lo1);
        uint32_t a2 = packh2f2(hi0);
        uint32_t a3 = packh2f2(hi1);
        const int kh0 = kc * 8;
        #pragma unroll
        for (int nt = 0; nt < 8; ++nt) {
            uint32_t b0 = Ws_h[(kh0 + tig)     * 72 + nt * 8 + gid];
            uint32_t b1 = Ws_h[(kh0 + 4 + tig) * 72 + nt * 8 + gid];
            asm("mma.sync.aligned.m16n8k16.row.col.f32.f16.f16.f32 "
                "{%0,%1,%2,%3}, {%4,%5,%6,%7}, {%8,%9}, {%0,%1,%2,%3};"
                : "+f"(acc[nt][0]), "+f"(acc[nt][1]),
                  "+f"(acc[nt][2]), "+f"(acc[nt][3])
                : "r"(a0), "r"(a1), "r"(a2), "r"(a3), "r"(b0), "r"(b1));
        }
        __syncthreads();
    }

    int row0 = rowBase + r0 + gid;
    int row1 = row0 + 8;
    #pragma unroll
    for (int nt = 0; nt < 8; ++nt) {
        int c = nt * 4 + tig;
        if (row0 < N) g_hs[(size_t)row0 * 32 + c] = __floats2half2_rn(acc[nt][0], acc[nt][1]);
        if (row1 < N) g_hs[(size_t)row1 * 32 + c] = __floats2half2_rn(acc[nt][2], acc[nt][3]);
    }
}

// ---------------------------------------------------------------------------
// Layer-1 aggregation + epilogue + layer-2 GEMV, fused.
// TWO nodes per warp: half-warp h owns node 2*warp+h; lane q (0..15) owns
// features 4q..4q+3 (one uint2 = 2 half2, 8B contiguous -> LDG.64; 16 lanes
// x 8B = one 128B line per neighbor row). ~2.75 instr/feature vs 3.5 before,
// and ~40% fewer warp-LDG issues.
__global__ void k_agg1(const float* __restrict__ b1,
                       const float* __restrict__ W2, int N) {
    int gw = (blockIdx.x * blockDim.x + threadIdx.x) >> 5;
    int lane = threadIdx.x & 31;
    int h = lane >> 4;          // half id 0/1
    int q = lane & 15;          // lane within half
    int w = gw * 2 + h;         // node
    bool valid = w < N;
    int wi = valid ? w : 0;

    int deg = valid ? g_cur[wi] : 0;
    float dv = rsqrtf((float)deg + 1.0f);
    int cnt = valid ? min(deg, SLOT_CAP) : 0;

    // self-loop seed: features 4q..4q+3
    uint2 hv = *(const uint2*)&g_hs[(size_t)wi * 32 + 2 * q];
    float2 f0 = __half22float2(*(__half2*)&hv.x);
    float2 f1 = __half22float2(*(__half2*)&hv.y);
    float4 a = make_float4(f0.x * dv, f0.y * dv, f1.x * dv, f1.y * dv);
    if (!valid) a = make_float4(0.f, 0.f, 0.f, 0.f);

    // warp loops to the max trip count of its two halves; padding lanes carry
    // dvs = 0 so their (valid-address) gathers contribute nothing.
    int cntO = __shfl_xor_sync(0xffffffffu, cnt, 16);
    int cm = max(cnt, cntO);
    const int* slots = &g_slots[(size_t)wi * SLOT_CAP];

    for (int j0 = 0; j0 < cm; j0 += 16) {
        int m = min(16, cm - j0);
        int s = 0; float dvs = 0.f;
        if (j0 + q < cnt) {
            s = slots[j0 + q];
            dvs = rsqrtf((float)g_cur[s] + 1.0f);
        }
        #pragma unroll 16
        for (int i = 0; i < m; ++i) {
            int   si  = __shfl_sync(0xffffffffu, s,   i, 16);
            float dvi = __shfl_sync(0xffffffffu, dvs, i, 16);
            uint2 nv = *(const uint2*)&g_hs[(size_t)si * 32 + 2 * q];
            float2 n0 = __half22float2(*(__half2*)&nv.x);
            float2 n1 = __half22float2(*(__half2*)&nv.y);
            a.x = fmaf(n0.x, dvi, a.x);
            a.y = fmaf(n0.y, dvi, a.y);
            a.z = fmaf(n1.x, dvi, a.z);
            a.w = fmaf(n1.y, dvi, a.w);
        }
    }
    float h0 = fmaxf(fmaf(dv, a.x, __ldg(&b1[4 * q])),     0.0f);
    float h1 = fmaxf(fmaf(dv, a.y, __ldg(&b1[4 * q + 1])), 0.0f);
    float h2 = fmaxf(fmaf(dv, a.z, __ldg(&b1[4 * q + 2])), 0.0f);
    float h3 = fmaxf(fmaf(dv, a.w, __ldg(&b1[4 * q + 3])), 0.0f);
    float z = h0 * __ldg(&W2[4 * q])     + h1 * __ldg(&W2[4 * q + 1])
            + h2 * __ldg(&W2[4 * q + 2]) + h3 * __ldg(&W2[4 * q + 3]);
    #pragma unroll
    for (int o = 8; o > 0; o >>= 1) z += __shfl_down_sync(0xffffffffu, z, o, 16);
    if (q == 0 && valid) g_zs[w] = dv * z;
}

// ---------------------------------------------------------------------------
// Layer-2 scalar aggregation + finalize. EIGHT lanes per node (best measured).
// Lane 0 restores g_cur[v] = 0 for the next graph replay.
__global__ void k_agg2(float* __restrict__ out, const float* __restrict__ b2, int N) {
    int idx = blockIdx.x * blockDim.x + threadIdx.x;
    int v = idx >> 3;
    int l = idx & 7;
    if (v >= N) return;
    int deg = g_cur[v];
    int cnt = min(deg, SLOT_CAP);
    const int* slots = &g_slots[(size_t)v * SLOT_CAP];
    float sum = 0.0f;
    for (int j = l; j < cnt; j += 8) sum += g_zs[slots[j]];
    #pragma unroll
    for (int o = 4; o > 0; o >>= 1) sum += __shfl_down_sync(0xffffffffu, sum, o, 8);
    if (l == 0) {
        sum += g_zs[v];    // self loop
        out[v] = fmaf(rsqrtf((float)deg + 1.0f), sum, __ldg(b2));
        g_cur[v] = 0;      // maintain all-zeros invariant for next call
    }
}

// ---------------------------------------------------------------------------
extern "C" void kernel_launch(void* const* d_in, const int* in_sizes, int n_in,
                              void* d_out, int out_size) {
    const float* x  = (const float*)d_in[0];
    const int*   ei = (const int*)d_in[1];      // edge_index int32
    const float* W1 = (const float*)d_in[2];
    const float* b1 = (const float*)d_in[3];
    const float* W2 = (const float*)d_in[4];
    const float* b2 = (const float*)d_in[5];
    float*       out = (float*)d_out;

    const int N = in_sizes[0] / FIN;
    const int E = in_sizes[1] / 2;

    cudaStream_t s2;
    cudaStreamCreateWithFlags(&s2, cudaStreamNonBlocking);
    cudaEvent_t eFork, eJoin;
    cudaEventCreateWithFlags(&eFork, cudaEventDisableTiming);
    cudaEventCreateWithFlags(&eJoin, cudaEventDisableTiming);

    cudaEventRecord(eFork, 0);
    cudaStreamWaitEvent(s2, eFork, 0);
    k_gemm<<<(N + 127) / 128, 256, 0, s2>>>(x, W1, N);
    cudaEventRecord(eJoin, s2);

    k_scatter<<<(E + 1023) / 1024, 256>>>(ei, E, N);

    cudaStreamWaitEvent(0, eJoin, 0);
    {
        int warps = (N + 1) / 2;
        k_agg1<<<(warps * 32 + 255) / 256, 256>>>(b1, W2, N);
    }
    k_agg2<<<(N * 8 + 255) / 256, 256>>>(out, b2, N);
}